// round 10
// baseline (speedup 1.0000x reference)
#include <cuda_runtime.h>

#define NT 128
#define RPC 256                 // rows per CTA (2 per thread)
#define STEPS 15
#define SPEED 5.0f
#define NCOLS_IN 18
#define NCOLS_OUT 178
#define CB 36                   // staged cols per row (30 used); 144B stride: 16B-aligned, bank-conflict-free
#define SMEM_BYTES (RPC * CB * 4)

// Warp-private flush: warp w flushes rows [32w,32w+32) and [128+32w,+32).
// Data staged at slot offset SOFF (floats), NC cols (even), to out col base_col.
template <int NC, int SOFF>
__device__ __forceinline__ void warp_flush(float* __restrict__ out,
                                           const float* __restrict__ stage,
                                           int R0, int rows_blk, int base_col,
                                           int w, int l)
{
    constexpr int NC2 = NC / 2;
    constexpr int ITERS = (32 * NC2 + 31) / 32;
    #pragma unroll
    for (int g = 0; g < 2; g++) {
        const int lrbase = g * NT + 32 * w;
        #pragma unroll
        for (int it = 0; it < ITERS; it++) {
            int idx = it * 32 + l;
            int r = idx / NC2;
            int k = idx - r * NC2;
            int lr = lrbase + r;
            if (r < 32 && lr < rows_blk) {
                float2 v = *(const float2*)(stage + lr * CB + SOFF + 2 * k);
                *(float2*)(out + (long long)(R0 + lr) * NCOLS_OUT + base_col + 2 * k) = v;
            }
        }
    }
}

__global__ void __launch_bounds__(NT) prog_kernel(
    const float* __restrict__ x,
    const float* __restrict__ c1w, const float* __restrict__ c1b,
    const float* __restrict__ c2w, const float* __restrict__ c2b,
    const float* __restrict__ l1w, const float* __restrict__ l1b,
    const float* __restrict__ l2w, const float* __restrict__ l2b,
    float* __restrict__ out, int n)
{
    extern __shared__ float s_rows[];   // RPC * CB staging (warp-private regions)

    // Pair-packed weights: 16 blocks of 20 floats (80B, 16B-aligned).
    __shared__ float s_w[16 * 20];
    __shared__ float s_cb[12];

    const int t = threadIdx.x;
    const int w = t >> 5, l = t & 31;

    if (t < 32) {
        const int j = t;
        const int base = 20 * (j >> 1) + 10 * (j & 1);
        s_w[base + 0] = l1w[0 * 32 + j];
        s_w[base + 1] = l1w[1 * 32 + j];
        s_w[base + 2] = l1w[2 * 32 + j];
        s_w[base + 3] = l1w[3 * 32 + j];
        s_w[base + 4] = l1b[j];
        s_w[base + 5] = l2w[5 * j + 0];
        s_w[base + 6] = l2w[5 * j + 1];
        s_w[base + 7] = l2w[5 * j + 2];
        s_w[base + 8] = l2w[5 * j + 3];
        s_w[base + 9] = l2w[5 * j + 4];
    } else if (t < 64) {
        const int u = t - 32;
        if (u < 12) {
            float v;
            if      (u == 0) v = c1w[0];
            else if (u == 1) v = c1w[1];
            else if (u == 2) v = c1b[0];
            else if (u == 3) v = c2w[0];
            else if (u == 4) v = c2w[1];
            else if (u == 5) v = c2b[0];
            else if (u < 11) v = l2b[u - 6];
            else             v = 0.0f;
            s_cb[u] = v;
        }
    }
    __syncthreads();   // only block-wide barrier: weights ready

    const int R0 = blockIdx.x * RPC;
    int rows_blk = n - R0; if (rows_blk > RPC) rows_blk = RPC;

    const float c1w0 = s_cb[0], c1w1 = s_cb[1], c1b0 = s_cb[2];
    const float c2w0 = s_cb[3], c2w1 = s_cb[4], c2b0 = s_cb[5];
    const float l2b0 = s_cb[6], l2b1 = s_cb[7], l2b2 = s_cb[8];
    const float l2b3 = s_cb[9], l2b4 = s_cb[10];

    float s0[2], s1[2], s2[2], s3[2], s4[2], s5[2], s6[2], s7[2], s8[2],
          s9[2], s10[2], s11[2], s12[2], s13[2], s14[2], s15[2], s16[2], s17[2];
    float* my[2];

    #pragma unroll
    for (int r = 0; r < 2; r++) {
        const int lr = t + r * NT;
        const int row = R0 + ((lr < rows_blk) ? lr : 0);
        my[r] = s_rows + lr * CB;
        const float* xr = x + (long long)row * NCOLS_IN;
        float2 v0 = *(const float2*)(xr + 0);
        float2 v1 = *(const float2*)(xr + 2);
        float2 v2 = *(const float2*)(xr + 4);
        float2 v3 = *(const float2*)(xr + 6);
        float2 v4 = *(const float2*)(xr + 8);
        float2 v8 = *(const float2*)(xr + 16);
        s0[r] = v0.x; s1[r] = v0.y; s2[r] = v1.x; s3[r] = v1.y;
        s4[r] = v2.x; s5[r] = v2.y; s6[r] = v3.x; s7[r] = v3.y;
        s8[r] = v4.x; s9[r] = v4.y; s17[r] = v8.y;
        float d13 = s1[r] - s3[r], d24 = s2[r] - s4[r];
        s10[r] = fmaf(d13, d13, d24 * d24);
        s11[r] = s12[r] = s13[r] = s14[r] = s15[r] = s16[r] = 0.0f;
    }

    auto stash = [&](int r, float* slot) {
        *(float2*)(slot + 0) = make_float2(s10[r], s1[r]);
        *(float2*)(slot + 2) = make_float2(s2[r], s3[r]);
        *(float2*)(slot + 4) = make_float2(s4[r], s5[r]);
        *(float2*)(slot + 6) = make_float2(s6[r], s7[r]);
        *(float2*)(slot + 8) = make_float2(s8[r], s17[r]);
    };

    auto do_step = [&](int slot_off) {
        float h20[2], h21[2], h22[2], h23[2];
        float p0[2], p1[2], p2[2], p3[2], p4[2];

        #pragma unroll
        for (int r = 0; r < 2; r++) {
            const float f0 = s1[r], f1 = s2[r], f2 = s3[r], f3 = s4[r],
                        f4 = s9[r], f5 = s17[r];
            float h10 = fmaxf(fmaf(c1w1, f1, fmaf(c1w0, f0, c1b0)), 0.0f);
            float h11 = fmaxf(fmaf(c1w1, f2, fmaf(c1w0, f1, c1b0)), 0.0f);
            float h12 = fmaxf(fmaf(c1w1, f3, fmaf(c1w0, f2, c1b0)), 0.0f);
            float h13 = fmaxf(fmaf(c1w1, f4, fmaf(c1w0, f3, c1b0)), 0.0f);
            float h14 = fmaxf(fmaf(c1w1, f5, fmaf(c1w0, f4, c1b0)), 0.0f);
            h20[r] = fmaxf(fmaf(c2w1, h11, fmaf(c2w0, h10, c2b0)), 0.0f);
            h21[r] = fmaxf(fmaf(c2w1, h12, fmaf(c2w0, h11, c2b0)), 0.0f);
            h22[r] = fmaxf(fmaf(c2w1, h13, fmaf(c2w0, h12, c2b0)), 0.0f);
            h23[r] = fmaxf(fmaf(c2w1, h14, fmaf(c2w0, h13, c2b0)), 0.0f);
            p0[r] = l2b0; p1[r] = l2b1; p2[r] = l2b2; p3[r] = l2b3; p4[r] = l2b4;
        }

        #pragma unroll 8
        for (int q = 0; q < 16; q++) {
            const float4 a0 = *(const float4*)(s_w + 20 * q + 0);
            const float4 a1 = *(const float4*)(s_w + 20 * q + 4);
            const float4 a2 = *(const float4*)(s_w + 20 * q + 8);
            const float4 a3 = *(const float4*)(s_w + 20 * q + 12);
            const float4 a4 = *(const float4*)(s_w + 20 * q + 16);

            #pragma unroll
            for (int r = 0; r < 2; r++) {
                float h3a = fmaf(h23[r], a0.w,
                            fmaf(h22[r], a0.z,
                            fmaf(h21[r], a0.y,
                            fmaf(h20[r], a0.x, a1.x))));
                h3a = fmaxf(h3a, 0.0f);
                p0[r] = fmaf(h3a, a1.y, p0[r]);
                p1[r] = fmaf(h3a, a1.z, p1[r]);
                p2[r] = fmaf(h3a, a1.w, p2[r]);
                p3[r] = fmaf(h3a, a2.x, p3[r]);
                p4[r] = fmaf(h3a, a2.y, p4[r]);

                float h3b = fmaf(h23[r], a3.y,
                            fmaf(h22[r], a3.x,
                            fmaf(h21[r], a2.w,
                            fmaf(h20[r], a2.z, a3.z))));
                h3b = fmaxf(h3b, 0.0f);
                p0[r] = fmaf(h3b, a3.w, p0[r]);
                p1[r] = fmaf(h3b, a4.x, p1[r]);
                p2[r] = fmaf(h3b, a4.y, p2[r]);
                p3[r] = fmaf(h3b, a4.z, p3[r]);
                p4[r] = fmaf(h3b, a4.w, p4[r]);
            }
        }

        #pragma unroll
        for (int r = 0; r < 2; r++) {
            float q0 = 1.0f / (1.0f + expf(-p0[r]));
            float q1 = 1.0f / (1.0f + expf(-p1[r]));
            float q2 = 1.0f / (1.0f + expf(-p2[r]));
            float q3 = 1.0f / (1.0f + expf(-p3[r]));
            float q4 = 1.0f / (1.0f + expf(-p4[r]));

            s5[r] = q0; s6[r] = q1; s7[r] = q2; s8[r] = q3; s17[r] = q4;

            const float a = q1 - q0, b = q2 - q0, c = q3 - q0;
            const float d = q2 - q1, e = q3 - q1, f = q3 - q2;
            s11[r] = a; s12[r] = b; s13[r] = c;
            s14[r] = d; s15[r] = e; s16[r] = f;

            const float dx_c = (c <= 0.0f) ? 0.0f : SPEED;
            const float st_c = (c <= 0.0f) ? 0.0f : 3.0f;
            const float dx_f = (f <= 0.0f) ? 0.0f : SPEED;
            const float st_f = (f <= 0.0f) ? 2.0f : 3.0f;
            const float dx_e = (e <= 0.0f) ? -SPEED : SPEED;
            const float st_e = (e <= 0.0f) ? 1.0f : 3.0f;
            const float dx_b = (b <= 0.0f) ? dx_c : dx_f;
            const float st_b = (b <= 0.0f) ? st_c : st_f;
            const float dx_d = (d <= 0.0f) ? dx_e : dx_f;
            const float st_d = (d <= 0.0f) ? st_e : st_f;
            const float dx   = (a <= 0.0f) ? dx_b : dx_d;
            const float st   = (a <= 0.0f) ? st_b : st_d;

            s1[r] += dx;
            s9[r] = st;
            s2[r] += SPEED;
            s3[r] += SPEED;
            s0[r] += 1.0f;
            float d13 = s1[r] - s3[r], d24 = s2[r] - s4[r];
            s10[r] = fmaf(d13, d13, d24 * d24);

            stash(r, my[r] + slot_off);
        }
    };

    // Phase 1: traj0 + steps 0,1 (slots 0..29) -> cols 18..47
    #pragma unroll
    for (int r = 0; r < 2; r++) stash(r, my[r]);
    do_step(10);
    do_step(20);
    __syncwarp();
    warp_flush<30, 0>(out, s_rows, R0, rows_blk, 18, w, l);
    __syncwarp();

    // Phases 2..5: steps (2,3,4) (5,6,7) (8,9,10) (11,12,13) -> 30 cols each
    #pragma unroll 1
    for (int ph = 0; ph < 4; ph++) {
        do_step(0);
        do_step(10);
        do_step(20);
        __syncwarp();
        warp_flush<30, 0>(out, s_rows, R0, rows_blk, 48 + 30 * ph, w, l);
        __syncwarp();
    }

    // Phase 6: step 14 (slots 0..9 -> cols 168..177) + final state (slots 10..27 -> cols 0..17)
    do_step(0);
    #pragma unroll
    for (int r = 0; r < 2; r++) {
        float* m = my[r] + 10;
        *(float2*)(m + 0)  = make_float2(s0[r], s1[r]);
        *(float2*)(m + 2)  = make_float2(s2[r], s3[r]);
        *(float2*)(m + 4)  = make_float2(s4[r], s5[r]);
        *(float2*)(m + 6)  = make_float2(s6[r], s7[r]);
        *(float2*)(m + 8)  = make_float2(s8[r], s9[r]);
        *(float2*)(m + 10) = make_float2(s10[r], s11[r]);
        *(float2*)(m + 12) = make_float2(s12[r], s13[r]);
        *(float2*)(m + 14) = make_float2(s14[r], s15[r]);
        *(float2*)(m + 16) = make_float2(s16[r], s17[r]);
    }
    __syncwarp();
    warp_flush<10, 0>(out, s_rows, R0, rows_blk, 168, w, l);
    warp_flush<18, 10>(out, s_rows, R0, rows_blk, 0, w, l);
}

extern "C" void kernel_launch(void* const* d_in, const int* in_sizes, int n_in,
                              void* d_out, int out_size)
{
    const float* x   = (const float*)d_in[0];
    const float* c1w = (const float*)d_in[1];
    const float* c1b = (const float*)d_in[2];
    const float* c2w = (const float*)d_in[3];
    const float* c2b = (const float*)d_in[4];
    const float* l1w = (const float*)d_in[5];
    const float* l1b = (const float*)d_in[6];
    const float* l2w = (const float*)d_in[7];
    const float* l2b = (const float*)d_in[8];
    float* out = (float*)d_out;

    const int n = in_sizes[0] / NCOLS_IN;
    const int blocks = (n + RPC - 1) / RPC;
    prog_kernel<<<blocks, NT, SMEM_BYTES>>>(x, c1w, c1b, c2w, c2b,
                                            l1w, l1b, l2w, l2b, out, n);
}

// round 11
// speedup vs baseline: 1.0868x; 1.0868x over previous
#include <cuda_runtime.h>

#define NT 160
#define RPC 320                 // rows per CTA (2 per thread)
#define STEPS 15
#define SPEED 5.0f
#define NCOLS_IN 18
#define NCOLS_OUT 178
#define CB 42                   // staged cols per row (40 used); even -> 8B aligned slots
#define SMEM_BYTES (RPC * CB * 4)

template <int NC>
__device__ __forceinline__ void flush2(float* __restrict__ out,
                                       const float* __restrict__ stage,
                                       int R0, int rows_blk, int base_col, int t)
{
    constexpr int NC2 = NC / 2;          // NC even
    const unsigned total = (unsigned)rows_blk * NC2;
    for (unsigned idx = t; idx < total; idx += NT) {
        unsigned r = idx / NC2;
        unsigned k = idx - r * NC2;
        float2 v = *(const float2*)(stage + r * CB + 2 * k);
        *(float2*)(out + (long long)(R0 + r) * NCOLS_OUT + base_col + 2 * k) = v;
    }
}

__global__ void __launch_bounds__(NT) prog_kernel(
    const float* __restrict__ x,
    const float* __restrict__ c1w, const float* __restrict__ c1b,
    const float* __restrict__ c2w, const float* __restrict__ c2b,
    const float* __restrict__ l1w, const float* __restrict__ l1b,
    const float* __restrict__ l2w, const float* __restrict__ l2b,
    float* __restrict__ out, int n)
{
    extern __shared__ float s_rows[];   // RPC * CB staging

    // Pair-packed weights: 16 blocks of 20 floats (80B, 16B-aligned).
    __shared__ float s_w[16 * 20];
    __shared__ float s_cb[12];

    const int t = threadIdx.x;
    if (t < 32) {
        const int j = t;
        const int base = 20 * (j >> 1) + 10 * (j & 1);
        s_w[base + 0] = l1w[0 * 32 + j];
        s_w[base + 1] = l1w[1 * 32 + j];
        s_w[base + 2] = l1w[2 * 32 + j];
        s_w[base + 3] = l1w[3 * 32 + j];
        s_w[base + 4] = l1b[j];
        s_w[base + 5] = l2w[5 * j + 0];
        s_w[base + 6] = l2w[5 * j + 1];
        s_w[base + 7] = l2w[5 * j + 2];
        s_w[base + 8] = l2w[5 * j + 3];
        s_w[base + 9] = l2w[5 * j + 4];
    } else if (t < 64) {
        const int u = t - 32;
        if (u < 12) {
            float v;
            if      (u == 0) v = c1w[0];
            else if (u == 1) v = c1w[1];
            else if (u == 2) v = c1b[0];
            else if (u == 3) v = c2w[0];
            else if (u == 4) v = c2w[1];
            else if (u == 5) v = c2b[0];
            else if (u < 11) v = l2b[u - 6];
            else             v = 0.0f;
            s_cb[u] = v;
        }
    }
    __syncthreads();

    const int R0 = blockIdx.x * RPC;
    int rows_blk = n - R0; if (rows_blk > RPC) rows_blk = RPC;

    const float c1w0 = s_cb[0], c1w1 = s_cb[1], c1b0 = s_cb[2];
    const float c2w0 = s_cb[3], c2w1 = s_cb[4], c2b0 = s_cb[5];
    const float l2b0 = s_cb[6], l2b1 = s_cb[7], l2b2 = s_cb[8];
    const float l2b3 = s_cb[9], l2b4 = s_cb[10];

    // two rows per thread: local row ids t and t+NT
    float s0[2], s1[2], s2[2], s3[2], s4[2], s5[2], s6[2], s7[2], s8[2],
          s9[2], s10[2], s11[2], s12[2], s13[2], s14[2], s15[2], s16[2], s17[2];
    float* my[2];

    #pragma unroll
    for (int r = 0; r < 2; r++) {
        const int lr = t + r * NT;                       // local row in CTA
        const int row = R0 + ((lr < rows_blk) ? lr : 0); // clamp inactive
        my[r] = s_rows + lr * CB;
        const float* xr = x + (long long)row * NCOLS_IN;
        float2 v0 = *(const float2*)(xr + 0);
        float2 v1 = *(const float2*)(xr + 2);
        float2 v2 = *(const float2*)(xr + 4);
        float2 v3 = *(const float2*)(xr + 6);
        float2 v4 = *(const float2*)(xr + 8);
        float2 v8 = *(const float2*)(xr + 16);
        s0[r] = v0.x; s1[r] = v0.y; s2[r] = v1.x; s3[r] = v1.y;
        s4[r] = v2.x; s5[r] = v2.y; s6[r] = v3.x; s7[r] = v3.y;
        s8[r] = v4.x; s9[r] = v4.y; s17[r] = v8.y;
        float d13 = s1[r] - s3[r], d24 = s2[r] - s4[r];
        s10[r] = fmaf(d13, d13, d24 * d24);
        s11[r] = s12[r] = s13[r] = s14[r] = s15[r] = s16[r] = 0.0f;
    }

    auto stash = [&](int r, float* slot) {
        *(float2*)(slot + 0) = make_float2(s10[r], s1[r]);
        *(float2*)(slot + 2) = make_float2(s2[r], s3[r]);
        *(float2*)(slot + 4) = make_float2(s4[r], s5[r]);
        *(float2*)(slot + 6) = make_float2(s6[r], s7[r]);
        *(float2*)(slot + 8) = make_float2(s8[r], s17[r]);
    };

    auto do_step = [&](int slot_off) {
        float h20[2], h21[2], h22[2], h23[2];
        float p0[2], p1[2], p2[2], p3[2], p4[2];

        #pragma unroll
        for (int r = 0; r < 2; r++) {
            const float f0 = s1[r], f1 = s2[r], f2 = s3[r], f3 = s4[r],
                        f4 = s9[r], f5 = s17[r];
            float h10 = fmaxf(fmaf(c1w1, f1, fmaf(c1w0, f0, c1b0)), 0.0f);
            float h11 = fmaxf(fmaf(c1w1, f2, fmaf(c1w0, f1, c1b0)), 0.0f);
            float h12 = fmaxf(fmaf(c1w1, f3, fmaf(c1w0, f2, c1b0)), 0.0f);
            float h13 = fmaxf(fmaf(c1w1, f4, fmaf(c1w0, f3, c1b0)), 0.0f);
            float h14 = fmaxf(fmaf(c1w1, f5, fmaf(c1w0, f4, c1b0)), 0.0f);
            h20[r] = fmaxf(fmaf(c2w1, h11, fmaf(c2w0, h10, c2b0)), 0.0f);
            h21[r] = fmaxf(fmaf(c2w1, h12, fmaf(c2w0, h11, c2b0)), 0.0f);
            h22[r] = fmaxf(fmaf(c2w1, h13, fmaf(c2w0, h12, c2b0)), 0.0f);
            h23[r] = fmaxf(fmaf(c2w1, h14, fmaf(c2w0, h13, c2b0)), 0.0f);
            p0[r] = l2b0; p1[r] = l2b1; p2[r] = l2b2; p3[r] = l2b3; p4[r] = l2b4;
        }

        #pragma unroll 8
        for (int q = 0; q < 16; q++) {
            const float4 a0 = *(const float4*)(s_w + 20 * q + 0);
            const float4 a1 = *(const float4*)(s_w + 20 * q + 4);
            const float4 a2 = *(const float4*)(s_w + 20 * q + 8);
            const float4 a3 = *(const float4*)(s_w + 20 * q + 12);
            const float4 a4 = *(const float4*)(s_w + 20 * q + 16);

            #pragma unroll
            for (int r = 0; r < 2; r++) {
                float h3a = fmaf(h23[r], a0.w,
                            fmaf(h22[r], a0.z,
                            fmaf(h21[r], a0.y,
                            fmaf(h20[r], a0.x, a1.x))));
                h3a = fmaxf(h3a, 0.0f);
                p0[r] = fmaf(h3a, a1.y, p0[r]);
                p1[r] = fmaf(h3a, a1.z, p1[r]);
                p2[r] = fmaf(h3a, a1.w, p2[r]);
                p3[r] = fmaf(h3a, a2.x, p3[r]);
                p4[r] = fmaf(h3a, a2.y, p4[r]);

                float h3b = fmaf(h23[r], a3.y,
                            fmaf(h22[r], a3.x,
                            fmaf(h21[r], a2.w,
                            fmaf(h20[r], a2.z, a3.z))));
                h3b = fmaxf(h3b, 0.0f);
                p0[r] = fmaf(h3b, a3.w, p0[r]);
                p1[r] = fmaf(h3b, a4.x, p1[r]);
                p2[r] = fmaf(h3b, a4.y, p2[r]);
                p3[r] = fmaf(h3b, a4.z, p3[r]);
                p4[r] = fmaf(h3b, a4.w, p4[r]);
            }
        }

        #pragma unroll
        for (int r = 0; r < 2; r++) {
            float q0 = 1.0f / (1.0f + expf(-p0[r]));
            float q1 = 1.0f / (1.0f + expf(-p1[r]));
            float q2 = 1.0f / (1.0f + expf(-p2[r]));
            float q3 = 1.0f / (1.0f + expf(-p3[r]));
            float q4 = 1.0f / (1.0f + expf(-p4[r]));

            s5[r] = q0; s6[r] = q1; s7[r] = q2; s8[r] = q3; s17[r] = q4;

            const float a = q1 - q0, b = q2 - q0, c = q3 - q0;
            const float d = q2 - q1, e = q3 - q1, f = q3 - q2;
            s11[r] = a; s12[r] = b; s13[r] = c;
            s14[r] = d; s15[r] = e; s16[r] = f;

            const float dx_c = (c <= 0.0f) ? 0.0f : SPEED;
            const float st_c = (c <= 0.0f) ? 0.0f : 3.0f;
            const float dx_f = (f <= 0.0f) ? 0.0f : SPEED;
            const float st_f = (f <= 0.0f) ? 2.0f : 3.0f;
            const float dx_e = (e <= 0.0f) ? -SPEED : SPEED;
            const float st_e = (e <= 0.0f) ? 1.0f : 3.0f;
            const float dx_b = (b <= 0.0f) ? dx_c : dx_f;
            const float st_b = (b <= 0.0f) ? st_c : st_f;
            const float dx_d = (d <= 0.0f) ? dx_e : dx_f;
            const float st_d = (d <= 0.0f) ? st_e : st_f;
            const float dx   = (a <= 0.0f) ? dx_b : dx_d;
            const float st   = (a <= 0.0f) ? st_b : st_d;

            s1[r] += dx;
            s9[r] = st;
            s2[r] += SPEED;
            s3[r] += SPEED;
            s0[r] += 1.0f;
            float d13 = s1[r] - s3[r], d24 = s2[r] - s4[r];
            s10[r] = fmaf(d13, d13, d24 * d24);

            stash(r, my[r] + slot_off);
        }
    };

    // Phase 1: traj0 (slots 0..9) + steps 0..2 -> cols 18..57
    #pragma unroll
    for (int r = 0; r < 2; r++) stash(r, my[r]);
    #pragma unroll 1
    for (int step = 0; step < 3; step++)
        do_step(10 * (step + 1));
    __syncthreads();
    flush2<40>(out, s_rows, R0, rows_blk, 18, t);
    __syncthreads();

    // Phase 2: steps 3..6 -> cols 58..97
    #pragma unroll 1
    for (int step = 3; step < 7; step++)
        do_step(10 * (step - 3));
    __syncthreads();
    flush2<40>(out, s_rows, R0, rows_blk, 58, t);
    __syncthreads();

    // Phase 3: steps 7..10 -> cols 98..137
    #pragma unroll 1
    for (int step = 7; step < 11; step++)
        do_step(10 * (step - 7));
    __syncthreads();
    flush2<40>(out, s_rows, R0, rows_blk, 98, t);
    __syncthreads();

    // Phase 4: steps 11..14 -> cols 138..177
    #pragma unroll 1
    for (int step = 11; step < 15; step++)
        do_step(10 * (step - 11));
    __syncthreads();
    flush2<40>(out, s_rows, R0, rows_blk, 138, t);
    __syncthreads();

    // Phase 5: final state (18 cols) -> cols 0..17
    #pragma unroll
    for (int r = 0; r < 2; r++) {
        float* m = my[r];
        *(float2*)(m + 0)  = make_float2(s0[r], s1[r]);
        *(float2*)(m + 2)  = make_float2(s2[r], s3[r]);
        *(float2*)(m + 4)  = make_float2(s4[r], s5[r]);
        *(float2*)(m + 6)  = make_float2(s6[r], s7[r]);
        *(float2*)(m + 8)  = make_float2(s8[r], s9[r]);
        *(float2*)(m + 10) = make_float2(s10[r], s11[r]);
        *(float2*)(m + 12) = make_float2(s12[r], s13[r]);
        *(float2*)(m + 14) = make_float2(s14[r], s15[r]);
        *(float2*)(m + 16) = make_float2(s16[r], s17[r]);
    }
    __syncthreads();
    flush2<18>(out, s_rows, R0, rows_blk, 0, t);
}

extern "C" void kernel_launch(void* const* d_in, const int* in_sizes, int n_in,
                              void* d_out, int out_size)
{
    const float* x   = (const float*)d_in[0];
    const float* c1w = (const float*)d_in[1];
    const float* c1b = (const float*)d_in[2];
    const float* c2w = (const float*)d_in[3];
    const float* c2b = (const float*)d_in[4];
    const float* l1w = (const float*)d_in[5];
    const float* l1b = (const float*)d_in[6];
    const float* l2w = (const float*)d_in[7];
    const float* l2b = (const float*)d_in[8];
    float* out = (float*)d_out;

    cudaFuncSetAttribute(prog_kernel,
                         cudaFuncAttributeMaxDynamicSharedMemorySize, SMEM_BYTES);

    const int n = in_sizes[0] / NCOLS_IN;
    const int blocks = (n + RPC - 1) / RPC;
    prog_kernel<<<blocks, NT, SMEM_BYTES>>>(x, c1w, c1b, c2w, c2b,
                                            l1w, l1b, l2w, l2b, out, n);
}

// round 12
// speedup vs baseline: 1.1804x; 1.0861x over previous
#include <cuda_runtime.h>

#define NT 128
#define RPC 256                 // rows per CTA (2 per thread)
#define STEPS 15
#define SPEED 5.0f
#define NCOLS_IN 18
#define NCOLS_OUT 178
#define CBUF 22                 // 20 staged cols + 2 pad per buffer row
#define BUFO (RPC * CBUF)       // float offset of buffer B
#define SMEM_BYTES (2 * RPC * CBUF * 4)

template <int NC>
__device__ __forceinline__ void flush2(float* __restrict__ out,
                                       const float* __restrict__ stage,
                                       int R0, int rows_blk, int base_col, int t)
{
    constexpr int NC2 = NC / 2;          // NC even
    const unsigned total = (unsigned)rows_blk * NC2;
    for (unsigned idx = t; idx < total; idx += NT) {
        unsigned r = idx / NC2;
        unsigned k = idx - r * NC2;
        float2 v = *(const float2*)(stage + r * CBUF + 2 * k);
        *(float2*)(out + (long long)(R0 + r) * NCOLS_OUT + base_col + 2 * k) = v;
    }
}

__global__ void __launch_bounds__(NT) prog_kernel(
    const float* __restrict__ x,
    const float* __restrict__ c1w, const float* __restrict__ c1b,
    const float* __restrict__ c2w, const float* __restrict__ c2b,
    const float* __restrict__ l1w, const float* __restrict__ l1b,
    const float* __restrict__ l2w, const float* __restrict__ l2b,
    float* __restrict__ out, int n)
{
    extern __shared__ float s_rows[];   // 2 ping-pong staging buffers

    // Pair-packed weights: 16 blocks of 20 floats (80B, 16B-aligned).
    __shared__ float s_w[16 * 20];
    __shared__ float s_cb[12];

    const int t = threadIdx.x;
    if (t < 32) {
        const int j = t;
        const int base = 20 * (j >> 1) + 10 * (j & 1);
        s_w[base + 0] = l1w[0 * 32 + j];
        s_w[base + 1] = l1w[1 * 32 + j];
        s_w[base + 2] = l1w[2 * 32 + j];
        s_w[base + 3] = l1w[3 * 32 + j];
        s_w[base + 4] = l1b[j];
        s_w[base + 5] = l2w[5 * j + 0];
        s_w[base + 6] = l2w[5 * j + 1];
        s_w[base + 7] = l2w[5 * j + 2];
        s_w[base + 8] = l2w[5 * j + 3];
        s_w[base + 9] = l2w[5 * j + 4];
    } else if (t < 64) {
        const int u = t - 32;
        if (u < 12) {
            float v;
            if      (u == 0) v = c1w[0];
            else if (u == 1) v = c1w[1];
            else if (u == 2) v = c1b[0];
            else if (u == 3) v = c2w[0];
            else if (u == 4) v = c2w[1];
            else if (u == 5) v = c2b[0];
            else if (u < 11) v = l2b[u - 6];
            else             v = 0.0f;
            s_cb[u] = v;
        }
    }
    __syncthreads();

    const int R0 = blockIdx.x * RPC;
    int rows_blk = n - R0; if (rows_blk > RPC) rows_blk = RPC;

    const float c1w0 = s_cb[0], c1w1 = s_cb[1], c1b0 = s_cb[2];
    const float c2w0 = s_cb[3], c2w1 = s_cb[4], c2b0 = s_cb[5];
    const float l2b0 = s_cb[6], l2b1 = s_cb[7], l2b2 = s_cb[8];
    const float l2b3 = s_cb[9], l2b4 = s_cb[10];

    // two rows per thread: local row ids t and t+NT
    float s0[2], s1[2], s2[2], s3[2], s4[2], s5[2], s6[2], s7[2], s8[2],
          s9[2], s10[2], s11[2], s12[2], s13[2], s14[2], s15[2], s16[2], s17[2];
    float* myA[2];   // buffer A slots for my rows
    float* myB[2];   // buffer B slots

    #pragma unroll
    for (int r = 0; r < 2; r++) {
        const int lr = t + r * NT;
        const int row = R0 + ((lr < rows_blk) ? lr : 0);
        myA[r] = s_rows + lr * CBUF;
        myB[r] = myA[r] + BUFO;
        const float* xr = x + (long long)row * NCOLS_IN;
        float2 v0 = *(const float2*)(xr + 0);
        float2 v1 = *(const float2*)(xr + 2);
        float2 v2 = *(const float2*)(xr + 4);
        float2 v3 = *(const float2*)(xr + 6);
        float2 v4 = *(const float2*)(xr + 8);
        float2 v8 = *(const float2*)(xr + 16);
        s0[r] = v0.x; s1[r] = v0.y; s2[r] = v1.x; s3[r] = v1.y;
        s4[r] = v2.x; s5[r] = v2.y; s6[r] = v3.x; s7[r] = v3.y;
        s8[r] = v4.x; s9[r] = v4.y; s17[r] = v8.y;
        float d13 = s1[r] - s3[r], d24 = s2[r] - s4[r];
        s10[r] = fmaf(d13, d13, d24 * d24);
        s11[r] = s12[r] = s13[r] = s14[r] = s15[r] = s16[r] = 0.0f;
    }

    auto stash = [&](int r, float* slot) {
        *(float2*)(slot + 0) = make_float2(s10[r], s1[r]);
        *(float2*)(slot + 2) = make_float2(s2[r], s3[r]);
        *(float2*)(slot + 4) = make_float2(s4[r], s5[r]);
        *(float2*)(slot + 6) = make_float2(s6[r], s7[r]);
        *(float2*)(slot + 8) = make_float2(s8[r], s17[r]);
    };

    auto do_step = [&](float* sl0, float* sl1) {
        float h20[2], h21[2], h22[2], h23[2];
        float p0[2], p1[2], p2[2], p3[2], p4[2];

        #pragma unroll
        for (int r = 0; r < 2; r++) {
            const float f0 = s1[r], f1 = s2[r], f2 = s3[r], f3 = s4[r],
                        f4 = s9[r], f5 = s17[r];
            float h10 = fmaxf(fmaf(c1w1, f1, fmaf(c1w0, f0, c1b0)), 0.0f);
            float h11 = fmaxf(fmaf(c1w1, f2, fmaf(c1w0, f1, c1b0)), 0.0f);
            float h12 = fmaxf(fmaf(c1w1, f3, fmaf(c1w0, f2, c1b0)), 0.0f);
            float h13 = fmaxf(fmaf(c1w1, f4, fmaf(c1w0, f3, c1b0)), 0.0f);
            float h14 = fmaxf(fmaf(c1w1, f5, fmaf(c1w0, f4, c1b0)), 0.0f);
            h20[r] = fmaxf(fmaf(c2w1, h11, fmaf(c2w0, h10, c2b0)), 0.0f);
            h21[r] = fmaxf(fmaf(c2w1, h12, fmaf(c2w0, h11, c2b0)), 0.0f);
            h22[r] = fmaxf(fmaf(c2w1, h13, fmaf(c2w0, h12, c2b0)), 0.0f);
            h23[r] = fmaxf(fmaf(c2w1, h14, fmaf(c2w0, h13, c2b0)), 0.0f);
            p0[r] = l2b0; p1[r] = l2b1; p2[r] = l2b2; p3[r] = l2b3; p4[r] = l2b4;
        }

        #pragma unroll 8
        for (int q = 0; q < 16; q++) {
            const float4 a0 = *(const float4*)(s_w + 20 * q + 0);
            const float4 a1 = *(const float4*)(s_w + 20 * q + 4);
            const float4 a2 = *(const float4*)(s_w + 20 * q + 8);
            const float4 a3 = *(const float4*)(s_w + 20 * q + 12);
            const float4 a4 = *(const float4*)(s_w + 20 * q + 16);

            #pragma unroll
            for (int r = 0; r < 2; r++) {
                float h3a = fmaf(h23[r], a0.w,
                            fmaf(h22[r], a0.z,
                            fmaf(h21[r], a0.y,
                            fmaf(h20[r], a0.x, a1.x))));
                h3a = fmaxf(h3a, 0.0f);
                p0[r] = fmaf(h3a, a1.y, p0[r]);
                p1[r] = fmaf(h3a, a1.z, p1[r]);
                p2[r] = fmaf(h3a, a1.w, p2[r]);
                p3[r] = fmaf(h3a, a2.x, p3[r]);
                p4[r] = fmaf(h3a, a2.y, p4[r]);

                float h3b = fmaf(h23[r], a3.y,
                            fmaf(h22[r], a3.x,
                            fmaf(h21[r], a2.w,
                            fmaf(h20[r], a2.z, a3.z))));
                h3b = fmaxf(h3b, 0.0f);
                p0[r] = fmaf(h3b, a3.w, p0[r]);
                p1[r] = fmaf(h3b, a4.x, p1[r]);
                p2[r] = fmaf(h3b, a4.y, p2[r]);
                p3[r] = fmaf(h3b, a4.z, p3[r]);
                p4[r] = fmaf(h3b, a4.w, p4[r]);
            }
        }

        #pragma unroll
        for (int r = 0; r < 2; r++) {
            float q0 = 1.0f / (1.0f + expf(-p0[r]));
            float q1 = 1.0f / (1.0f + expf(-p1[r]));
            float q2 = 1.0f / (1.0f + expf(-p2[r]));
            float q3 = 1.0f / (1.0f + expf(-p3[r]));
            float q4 = 1.0f / (1.0f + expf(-p4[r]));

            s5[r] = q0; s6[r] = q1; s7[r] = q2; s8[r] = q3; s17[r] = q4;

            const float a = q1 - q0, b = q2 - q0, c = q3 - q0;
            const float d = q2 - q1, e = q3 - q1, f = q3 - q2;
            s11[r] = a; s12[r] = b; s13[r] = c;
            s14[r] = d; s15[r] = e; s16[r] = f;

            const float dx_c = (c <= 0.0f) ? 0.0f : SPEED;
            const float st_c = (c <= 0.0f) ? 0.0f : 3.0f;
            const float dx_f = (f <= 0.0f) ? 0.0f : SPEED;
            const float st_f = (f <= 0.0f) ? 2.0f : 3.0f;
            const float dx_e = (e <= 0.0f) ? -SPEED : SPEED;
            const float st_e = (e <= 0.0f) ? 1.0f : 3.0f;
            const float dx_b = (b <= 0.0f) ? dx_c : dx_f;
            const float st_b = (b <= 0.0f) ? st_c : st_f;
            const float dx_d = (d <= 0.0f) ? dx_e : dx_f;
            const float st_d = (d <= 0.0f) ? st_e : st_f;
            const float dx   = (a <= 0.0f) ? dx_b : dx_d;
            const float st   = (a <= 0.0f) ? st_b : st_d;

            s1[r] += dx;
            s9[r] = st;
            s2[r] += SPEED;
            s3[r] += SPEED;
            s0[r] += 1.0f;
            float d13 = s1[r] - s3[r], d24 = s2[r] - s4[r];
            s10[r] = fmaf(d13, d13, d24 * d24);

            stash(r, r == 0 ? sl0 : sl1);
        }
    };

    // Prologue: traj0 -> A[0..9], step 0 -> A[10..19]  (cols 18..37)
    #pragma unroll
    for (int r = 0; r < 2; r++) stash(r, myA[r]);
    do_step(myA[0] + 10, myA[1] + 10);
    __syncthreads();

    // Ping-pong phases: ph=0..6, flush one buffer while computing 2 steps into the other.
    //   ph even: flush A, write B;  ph odd: flush B, write A.
    //   flush cols: 18+20*(ph+0)?  ph=0 flushes A (traj0+step0) -> cols 18..37.
    #pragma unroll 1
    for (int ph = 0; ph < 7; ph++) {
        const float* fbuf = s_rows + ((ph & 1) ? BUFO : 0);
        flush2<20>(out, fbuf, R0, rows_blk, 18 + 20 * ph, t);

        float* w0 = (ph & 1) ? myA[0] : myB[0];
        float* w1 = (ph & 1) ? myA[1] : myB[1];
        do_step(w0, w1);            // step 2ph+1 -> slots 0..9
        do_step(w0 + 10, w1 + 10);  // step 2ph+2 -> slots 10..19
        __syncthreads();
    }

    // ph=7: flush B (steps 13,14) -> cols 158..177; stash final state -> A[0..17]
    flush2<20>(out, s_rows + BUFO, R0, rows_blk, 158, t);
    #pragma unroll
    for (int r = 0; r < 2; r++) {
        float* m = myA[r];
        *(float2*)(m + 0)  = make_float2(s0[r], s1[r]);
        *(float2*)(m + 2)  = make_float2(s2[r], s3[r]);
        *(float2*)(m + 4)  = make_float2(s4[r], s5[r]);
        *(float2*)(m + 6)  = make_float2(s6[r], s7[r]);
        *(float2*)(m + 8)  = make_float2(s8[r], s9[r]);
        *(float2*)(m + 10) = make_float2(s10[r], s11[r]);
        *(float2*)(m + 12) = make_float2(s12[r], s13[r]);
        *(float2*)(m + 14) = make_float2(s14[r], s15[r]);
        *(float2*)(m + 16) = make_float2(s16[r], s17[r]);
    }
    __syncthreads();

    // Final: flush A (18 cols) -> cols 0..17
    flush2<18>(out, s_rows, R0, rows_blk, 0, t);
}

extern "C" void kernel_launch(void* const* d_in, const int* in_sizes, int n_in,
                              void* d_out, int out_size)
{
    const float* x   = (const float*)d_in[0];
    const float* c1w = (const float*)d_in[1];
    const float* c1b = (const float*)d_in[2];
    const float* c2w = (const float*)d_in[3];
    const float* c2b = (const float*)d_in[4];
    const float* l1w = (const float*)d_in[5];
    const float* l1b = (const float*)d_in[6];
    const float* l2w = (const float*)d_in[7];
    const float* l2b = (const float*)d_in[8];
    float* out = (float*)d_out;

    const int n = in_sizes[0] / NCOLS_IN;
    const int blocks = (n + RPC - 1) / RPC;
    prog_kernel<<<blocks, NT, SMEM_BYTES>>>(x, c1w, c1b, c2w, c2b,
                                            l1w, l1b, l2w, l2b, out, n);
}